// round 16
// baseline (speedup 1.0000x reference)
#include <cuda_runtime.h>
#include <math.h>
#include <float.h>
#include <stdint.h>

#define BB      64
#define TT      100
#define NQ      (BB * TT)          // 6400 queries (flat)
#define NN      20000
#define NCH     16
#define CH_PTS  1250               // real points per chunk
#define CH_PAD  1280               // padded points per chunk
#define CH_PAIR 640                // pairs per chunk
#define WARPS   8
#define WPAIR   (CH_PAIR / WARPS)  // 80 pairs per warp
#define SEGPAIR 16                 // pairs per segment
#define NSEG    (WPAIR / SEGPAIR)  // 5 segments per warp
#define NTILE   (NQ / 128)         // 50 query tiles
#define THREADS 256
#define RBLK    128
#define NRED    (NQ / RBLK)        // 50 reduce CTAs (thread per query)

// Scratch (no device allocation allowed).
// g_key[q] holds ~((sortable(qmin)<<32)|n): atomicMax == lexicographic argmin
// (min value, then lowest n). Zero-initialized; any real key is > 0; reduce
// resets to 0 after consuming -> graph-replay safe, fully deterministic.
__device__ unsigned long long g_key[NQ];
__device__ float g_part[NRED];
__device__ int   g_cnt = 0;          // threadfence-reduction counter (self-reset)

// ---- packed f32x2 helpers -------------------------------------------------
__device__ __forceinline__ uint64_t ffma2(uint64_t a, uint64_t b, uint64_t c) {
    uint64_t d;
    asm("fma.rn.f32x2 %0, %1, %2, %3;" : "=l"(d) : "l"(a), "l"(b), "l"(c));
    return d;
}
__device__ __forceinline__ uint64_t pack2(float v) {
    uint64_t r;
    asm("mov.b64 %0, {%1, %1};" : "=l"(r) : "f"(v));
    return r;
}
__device__ __forceinline__ void unpack2(float& lo, float& hi, uint64_t v) {
    asm("mov.b64 {%0, %1}, %2;" : "=f"(lo), "=f"(hi) : "l"(v));
}
__device__ __forceinline__ void lds_v2b64(uint64_t& a, uint64_t& b, uint32_t addr) {
    asm volatile("ld.shared.v2.b64 {%0, %1}, [%2];" : "=l"(a), "=l"(b) : "r"(addr));
}
__device__ __forceinline__ uint32_t smem_u32(const void* p) {
    uint32_t a;
    asm("{ .reg .u64 t; cvta.to.shared.u64 t, %1; cvt.u32.u64 %0, t; }"
        : "=r"(a) : "l"(p));
    return a;
}

// Strictly monotone float -> uint32 (IEEE total order for non-NaN).
__device__ __forceinline__ unsigned int f32_sortable(float f) {
    unsigned int b = __float_as_uint(f);
    return (b & 0x80000000u) ? ~b : (b | 0x80000000u);
}

// Query transform: local waypoint -> NEGATED global point. The exact same fmaf
// chain is used in scan and rescan (bitwise-identical for equality recovery).
__device__ __forceinline__ void query_transform(
    const float* __restrict__ poses, const float* __restrict__ wpts, int qid,
    float& nwx, float& nwy, float& nwz)
{
    const float* P = poses + (qid / TT) * 16;
    const float* w = wpts + qid * 3;
    const float wx = w[0], wy = w[1], wz = w[2];
    nwx = -fmaf(P[0], wx, fmaf(P[1], wy, fmaf(P[2],  wz, P[3])));
    nwy = -fmaf(P[4], wx, fmaf(P[5], wy, fmaf(P[6],  wz, P[7])));
    nwz = -fmaf(P[8], wx, fmaf(P[9], wy, fmaf(P[10], wz, P[11])));
}

// ---------------------------------------------------------------------------
// NN kernel (R11 mainloop, unchanged): CTA = (chunk, query-tile), grid 800,
// 256 threads, 4 CTAs/SM. After the cross-warp reduce, each of the 128 winner
// threads rescans its winning 32-pt segment FROM SMEM (exact fmaf equality ->
// exact lowest-n index) and publishes the (value, n) via one 64-bit atomicMax
// per (query, chunk) on an inverted sortable key. No partial arrays at all.
// ---------------------------------------------------------------------------
__global__ void __launch_bounds__(THREADS, 4) nn_kernel(
    const float* __restrict__ poses,     // [B,4,4]
    const float* __restrict__ wpts,      // [B,T,3]
    const float* __restrict__ boundary)  // [4,N]
{
    __shared__ float s_pts[CH_PAD * 4];     // 20 KB, pair-interleaved
    __shared__ float s_qx[128], s_qy[128], s_qz[128];
    __shared__ float red_q[WARPS][128];     // 4 KB
    __shared__ int   red_s[WARPS][128];     // 4 KB (CTA-local pair start)

    const int ch   = blockIdx.x;
    const int tile = blockIdx.y;
    const int tid  = threadIdx.x;

    // Build chunk tile
    const int gbase = ch * CH_PTS;
    for (int i = tid; i < CH_PAD; i += THREADS) {
        float x = 0.0f, y = 0.0f, z = 0.0f, c = 1e30f;   // pad never wins
        if (i < CH_PTS) {
            x = boundary[0 * NN + gbase + i];
            y = boundary[1 * NN + gbase + i];
            z = boundary[2 * NN + gbase + i];
            c = 0.5f * fmaf(x, x, fmaf(y, y, z * z));
        }
        const int m = i >> 1, h = i & 1;
        s_pts[m * 8 + 0 + h] = x;
        s_pts[m * 8 + 2 + h] = y;
        s_pts[m * 8 + 4 + h] = z;
        s_pts[m * 8 + 6 + h] = c;
    }
    if (tid < 128) {
        float nwx, nwy, nwz;
        query_transform(poses, wpts, tile * 128 + tid, nwx, nwy, nwz);
        s_qx[tid] = nwx; s_qy[tid] = nwy; s_qz[tid] = nwz;
    }
    __syncthreads();

    const int warp = tid >> 5;
    const int lane = tid & 31;

    uint64_t nwx2[4], nwy2[4], nwz2[4];
    #pragma unroll
    for (int j = 0; j < 4; ++j) {
        const int sl = lane + 32 * j;
        nwx2[j] = pack2(s_qx[sl]);
        nwy2[j] = pack2(s_qy[sl]);
        nwz2[j] = pack2(s_qz[sl]);
    }

    float best[4];
    int   sid[4];
    #pragma unroll
    for (int j = 0; j < 4; ++j) { best[j] = FLT_MAX; sid[j] = 0; }

    const uint32_t wbase = smem_u32(s_pts) + (uint32_t)(warp * WPAIR) * 32u;

    #pragma unroll
    for (int s = 0; s < NSEG; ++s) {
        const uint32_t segb = wbase + (uint32_t)(s * SEGPAIR) * 32u;
        float svlo[4], svhi[4];
        #pragma unroll
        for (int j = 0; j < 4; ++j) { svlo[j] = FLT_MAX; svhi[j] = FLT_MAX; }

        #pragma unroll 4
        for (int pp = 0; pp < SEGPAIR; ++pp) {
            uint64_t xx, yy, zz, cc;
            lds_v2b64(xx, yy, segb + pp * 32u);        // broadcast, conflict-free
            lds_v2b64(zz, cc, segb + pp * 32u + 16u);
            #pragma unroll
            for (int j = 0; j < 4; ++j) {
                uint64_t q = ffma2(nwx2[j], xx,
                             ffma2(nwy2[j], yy,
                             ffma2(nwz2[j], zz, cc)));
                float qlo, qhi;
                unpack2(qlo, qhi, q);                   // register alias, free
                svlo[j] = fminf(svlo[j], qlo);
                svhi[j] = fminf(svhi[j], qhi);
            }
        }
        #pragma unroll
        for (int j = 0; j < 4; ++j) {
            float m = fminf(svlo[j], svhi[j]);
            sid[j]  = (m < best[j]) ? s : sid[j];       // strict < -> first seg
            best[j] = fminf(best[j], m);
        }
    }

    #pragma unroll
    for (int j = 0; j < 4; ++j) {
        red_q[warp][lane + 32 * j] = best[j];
        red_s[warp][lane + 32 * j] = warp * WPAIR + sid[j] * SEGPAIR;  // local
    }
    __syncthreads();

    // Cross-warp reduce + in-SMEM exact index recovery + atomicMax publish.
    if (tid < 128) {
        float bq = red_q[0][tid];
        int   bs = red_s[0][tid];
        #pragma unroll
        for (int w = 1; w < WARPS; ++w) {
            float q = red_q[w][tid];
            int   s = red_s[w][tid];
            if (q < bq) { bq = q; bs = s; }   // strict < keeps lowest warp
        }

        // Rescan winning 32-pt segment from SMEM; exact fmaf-chain equality.
        const float nwx = s_qx[tid], nwy = s_qy[tid], nwz = s_qz[tid];
        int nloc = 0x7FFFFFFF;
        #pragma unroll 4
        for (int k = 0; k < SEGPAIR; ++k) {
            const int m = bs + k;
            const float* f = s_pts + m * 8;
            float q0 = fmaf(nwx, f[0], fmaf(nwy, f[2], fmaf(nwz, f[4], f[6])));
            float q1 = fmaf(nwx, f[1], fmaf(nwy, f[3], fmaf(nwz, f[5], f[7])));
            if (q1 == bq) nloc = min(nloc, m * 2 + 1);
            if (q0 == bq) nloc = min(nloc, m * 2);      // lowest local pt wins
        }
        const unsigned int n = (unsigned int)(gbase + nloc);

        const unsigned long long key =
            ((unsigned long long)f32_sortable(bq) << 32) | n;
        atomicMax(&g_key[tile * 128 + tid], ~key);      // max(~k) == min(k)
    }
}

// ---------------------------------------------------------------------------
// Reduce + final: THREAD per query (50 CTAs x 128). One 64-bit key load gives
// the exact winning index directly (no argmin, no rescan). Reset key to 0 for
// graph replay, fetch cp/cn, global-frame dot (rotation cancels), ExpRelu,
// fixed-order block sum; last CTA sums 50 partials.
// ---------------------------------------------------------------------------
__global__ void __launch_bounds__(RBLK) reduce_kernel(
    const float* __restrict__ poses,
    const float* __restrict__ wpts,
    const float* __restrict__ boundary,
    const float* __restrict__ nrms,      // [3,N] global normals
    float* __restrict__ out)
{
    const int tid = threadIdx.x;
    const int qid = blockIdx.x * RBLK + tid;

    const unsigned long long inv = g_key[qid];
    g_key[qid] = 0ULL;                              // replay-safe reset
    const int n = (int)(unsigned int)(~inv & 0xFFFFFFFFull);

    float nwx, nwy, nwz;
    query_transform(poses, wpts, qid, nwx, nwy, nwz);

    const float cpx = boundary[0 * NN + n];
    const float cpy = boundary[1 * NN + n];
    const float cpz = boundary[2 * NN + n];
    const float nx  = nrms[0 * NN + n];
    const float ny  = nrms[1 * NN + n];
    const float nz  = nrms[2 * NN + n];
    // global-frame dot: (wg - cp) . n_g  (rigid transform cancels)
    const float d = (-nwx - cpx) * nx + (-nwy - cpy) * ny + (-nwz - cpz) * nz;
    const float val = (d > 0.0f) ? (d + 1.0f) : expf(0.5f * d);  // ExpRelu

    __shared__ float acc[RBLK];
    acc[tid] = val;
    __syncthreads();
    #pragma unroll
    for (int o = RBLK / 2; o > 0; o >>= 1) {
        if (tid < o) acc[tid] += acc[tid + o];
        __syncthreads();
    }

    __shared__ int s_last;
    if (tid == 0) {
        g_part[blockIdx.x] = acc[0];
        __threadfence();
        const int old = atomicAdd(&g_cnt, 1);
        s_last = (old == NRED - 1) ? 1 : 0;
    }
    __syncthreads();

    if (s_last && tid == 0) {
        float s = 0.0f;
        #pragma unroll
        for (int k = 0; k < NRED; ++k) s += g_part[k];  // fixed ascending order
        out[0] = s * (1.0f / (float)NQ);
        g_cnt = 0;                                      // replay-safe reset
    }
}

// ---------------------------------------------------------------------------
extern "C" void kernel_launch(void* const* d_in, const int* in_sizes, int n_in,
                              void* d_out, int out_size)
{
    const float* poses    = (const float*)d_in[0];  // [64,4,4]
    const float* wpts     = (const float*)d_in[1];  // [64,100,3]
    const float* boundary = (const float*)d_in[2];  // [4,20000]
    const float* nrms     = (const float*)d_in[3];  // [3,20000]
    float* out = (float*)d_out;

    dim3 gridn(NCH, NTILE);
    nn_kernel<<<gridn, THREADS>>>(poses, wpts, boundary);
    reduce_kernel<<<NRED, RBLK>>>(poses, wpts, boundary, nrms, out);
}

// round 17
// speedup vs baseline: 1.1232x; 1.1232x over previous
#include <cuda_runtime.h>
#include <math.h>
#include <float.h>
#include <stdint.h>

#define BB      64
#define TT      100
#define NQ      (BB * TT)          // 6400 queries (flat)
#define NN      20000
#define NCH     16
#define CH_PTS  1250               // real points per chunk
#define CH_PAD  1280               // padded points per chunk
#define CH_PAIR 640                // pairs per chunk
#define WARPS   8
#define WPAIR   (CH_PAIR / WARPS)  // 80 pairs per warp
#define SEGPAIR 16                 // pairs per segment
#define NSEG    (WPAIR / SEGPAIR)  // 5 segments per warp
#define SEGPTS  (SEGPAIR * 2)      // 32 points per segment
#define NTILE   (NQ / 128)         // 50 query tiles
#define THREADS 256
#define QPW     2                  // queries per reduce warp
#define NRED    (NQ / (8 * QPW))   // 400 reduce CTAs

// Scratch (no device allocation allowed)
__device__ float g_pmin[NQ * NCH];
__device__ int   g_ps0 [NQ * NCH];   // padded-index start of winning 32-pt segment
__device__ float g_part[NRED];
__device__ int   g_cnt = 0;          // threadfence-reduction counter (self-reset)

// ---- packed f32x2 helpers -------------------------------------------------
__device__ __forceinline__ uint64_t ffma2(uint64_t a, uint64_t b, uint64_t c) {
    uint64_t d;
    asm("fma.rn.f32x2 %0, %1, %2, %3;" : "=l"(d) : "l"(a), "l"(b), "l"(c));
    return d;
}
__device__ __forceinline__ uint64_t pack2(float v) {
    uint64_t r;
    asm("mov.b64 %0, {%1, %1};" : "=l"(r) : "f"(v));
    return r;
}
__device__ __forceinline__ void unpack2(float& lo, float& hi, uint64_t v) {
    asm("mov.b64 {%0, %1}, %2;" : "=f"(lo), "=f"(hi) : "l"(v));
}
__device__ __forceinline__ void lds_v2b64(uint64_t& a, uint64_t& b, uint32_t addr) {
    asm volatile("ld.shared.v2.b64 {%0, %1}, [%2];" : "=l"(a), "=l"(b) : "r"(addr));
}
__device__ __forceinline__ uint32_t smem_u32(const void* p) {
    uint32_t a;
    asm("{ .reg .u64 t; cvta.to.shared.u64 t, %1; cvt.u32.u64 %0, t; }"
        : "=r"(a) : "l"(p));
    return a;
}

// Query transform: local waypoint -> NEGATED global point. The exact same fmaf
// chain is used in scan and rescan (bitwise-identical for equality recovery).
__device__ __forceinline__ void query_transform(
    const float* __restrict__ poses, const float* __restrict__ wpts, int qid,
    float& nwx, float& nwy, float& nwz)
{
    const float* P = poses + (qid / TT) * 16;
    const float* w = wpts + qid * 3;
    const float wx = w[0], wy = w[1], wz = w[2];
    nwx = -fmaf(P[0], wx, fmaf(P[1], wy, fmaf(P[2],  wz, P[3])));
    nwy = -fmaf(P[4], wx, fmaf(P[5], wy, fmaf(P[6],  wz, P[7])));
    nwz = -fmaf(P[8], wx, fmaf(P[9], wy, fmaf(P[10], wz, P[11])));
}

// ---------------------------------------------------------------------------
// NN kernel: byte-identical to the proven R11 version (33.2 us total).
// CTA = (chunk, query-tile). Chunk tile (x,y,z,0.5|p|^2, pair-interleaved) +
// 128 query transforms in SMEM; 8 warps x 80 pairs, 4 query slots/lane,
// FFMA2 + dual FMNMX chains, 32-pt-segment argmin, cross-warp reduce.
// ---------------------------------------------------------------------------
__global__ void __launch_bounds__(THREADS, 4) nn_kernel(
    const float* __restrict__ poses,     // [B,4,4]
    const float* __restrict__ wpts,      // [B,T,3]
    const float* __restrict__ boundary)  // [4,N]
{
    __shared__ float s_pts[CH_PAD * 4];     // 20 KB, pair-interleaved
    __shared__ float s_qx[128], s_qy[128], s_qz[128];
    __shared__ float red_q[WARPS][128];     // 4 KB
    __shared__ int   red_s[WARPS][128];     // 4 KB

    const int ch   = blockIdx.x;
    const int tile = blockIdx.y;
    const int tid  = threadIdx.x;

    // Build chunk tile (identical math to reduce's recompute)
    const int gbase = ch * CH_PTS;
    for (int i = tid; i < CH_PAD; i += THREADS) {
        float x = 0.0f, y = 0.0f, z = 0.0f, c = 1e30f;   // pad never wins
        if (i < CH_PTS) {
            x = boundary[0 * NN + gbase + i];
            y = boundary[1 * NN + gbase + i];
            z = boundary[2 * NN + gbase + i];
            c = 0.5f * fmaf(x, x, fmaf(y, y, z * z));
        }
        const int m = i >> 1, h = i & 1;
        s_pts[m * 8 + 0 + h] = x;
        s_pts[m * 8 + 2 + h] = y;
        s_pts[m * 8 + 4 + h] = z;
        s_pts[m * 8 + 6 + h] = c;
    }
    if (tid < 128) {
        float nwx, nwy, nwz;
        query_transform(poses, wpts, tile * 128 + tid, nwx, nwy, nwz);
        s_qx[tid] = nwx; s_qy[tid] = nwy; s_qz[tid] = nwz;
    }
    __syncthreads();

    const int warp = tid >> 5;
    const int lane = tid & 31;

    uint64_t nwx2[4], nwy2[4], nwz2[4];
    #pragma unroll
    for (int j = 0; j < 4; ++j) {
        const int sl = lane + 32 * j;
        nwx2[j] = pack2(s_qx[sl]);
        nwy2[j] = pack2(s_qy[sl]);
        nwz2[j] = pack2(s_qz[sl]);
    }

    float best[4];
    int   sid[4];
    #pragma unroll
    for (int j = 0; j < 4; ++j) { best[j] = FLT_MAX; sid[j] = 0; }

    const uint32_t wbase = smem_u32(s_pts) + (uint32_t)(warp * WPAIR) * 32u;

    #pragma unroll
    for (int s = 0; s < NSEG; ++s) {
        const uint32_t segb = wbase + (uint32_t)(s * SEGPAIR) * 32u;
        float svlo[4], svhi[4];
        #pragma unroll
        for (int j = 0; j < 4; ++j) { svlo[j] = FLT_MAX; svhi[j] = FLT_MAX; }

        #pragma unroll 4
        for (int pp = 0; pp < SEGPAIR; ++pp) {
            uint64_t xx, yy, zz, cc;
            lds_v2b64(xx, yy, segb + pp * 32u);        // broadcast, conflict-free
            lds_v2b64(zz, cc, segb + pp * 32u + 16u);
            #pragma unroll
            for (int j = 0; j < 4; ++j) {
                uint64_t q = ffma2(nwx2[j], xx,
                             ffma2(nwy2[j], yy,
                             ffma2(nwz2[j], zz, cc)));
                float qlo, qhi;
                unpack2(qlo, qhi, q);                   // register alias, free
                svlo[j] = fminf(svlo[j], qlo);
                svhi[j] = fminf(svhi[j], qhi);
            }
        }
        #pragma unroll
        for (int j = 0; j < 4; ++j) {
            float m = fminf(svlo[j], svhi[j]);
            sid[j]  = (m < best[j]) ? s : sid[j];       // strict < -> first seg
            best[j] = fminf(best[j], m);
        }
    }

    #pragma unroll
    for (int j = 0; j < 4; ++j) {
        red_q[warp][lane + 32 * j] = best[j];
        red_s[warp][lane + 32 * j] =
            ch * CH_PAD + (warp * WPAIR + sid[j] * SEGPAIR) * 2;
    }
    __syncthreads();

    // Cross-warp reduce; strict < keeps lowest warp = lowest point index.
    if (tid < 128) {
        float bq = red_q[0][tid];
        int   bs = red_s[0][tid];
        #pragma unroll
        for (int w = 1; w < WARPS; ++w) {
            float q = red_q[w][tid];
            int   s = red_s[w][tid];
            if (q < bq) { bq = q; bs = s; }
        }
        const int qid = tile * 128 + tid;
        g_pmin[qid * NCH + ch] = bq;
        g_ps0 [qid * NCH + ch] = bs;
    }
}

// ---------------------------------------------------------------------------
// Reduce + final: warp handles TWO queries (independent chains -> latency
// overlap). Per query: coalesced 16-partial load + shuffle argmin (tie ->
// lowest segment start = lowest n); then ONE combined memory round -- each
// rescan lane loads its candidate point AND normal concurrently, computes the
// fmaf-chain value (exact equality) and its speculative ExpRelu value; after
// the nbest min-shuffle the winner's value is fetched with a single shfl.
// CTA sums 16 values fixed-order; last CTA sums 400 partials fixed-order.
// ---------------------------------------------------------------------------
__global__ void __launch_bounds__(THREADS) reduce_kernel(
    const float* __restrict__ poses,
    const float* __restrict__ wpts,
    const float* __restrict__ boundary,
    const float* __restrict__ nrms,      // [3,N] global normals
    float* __restrict__ out)
{
    const int warp = threadIdx.x >> 5;
    const int lane = threadIdx.x & 31;
    const int qbase = (blockIdx.x * 8 + warp) * QPW;

    float vq[QPW];
    #pragma unroll
    for (int u = 0; u < QPW; ++u) {
        const int qid = qbase + u;

        float nwx, nwy, nwz;
        query_transform(poses, wpts, qid, nwx, nwy, nwz);

        float vmin = FLT_MAX;
        int   s0   = 0x7FFFFFFF;
        if (lane < NCH) {
            vmin = g_pmin[qid * NCH + lane];
            s0   = g_ps0 [qid * NCH + lane];
        }
        #pragma unroll
        for (int off = 16; off > 0; off >>= 1) {
            float v2 = __shfl_xor_sync(0xFFFFFFFFu, vmin, off);
            int   s2 = __shfl_xor_sync(0xFFFFFFFFu, s0,   off);
            if (v2 < vmin || (v2 == vmin && s2 < s0)) { vmin = v2; s0 = s2; }
        }

        // Combined rescan + winner evaluation round (single memory round):
        const int ch   = s0 / CH_PAD;
        const int offb = s0 - ch * CH_PAD;
        const int base = ch * CH_PTS + offb;     // global n of lane 0
        const int o    = offb + lane;
        const bool ok  = (o < CH_PTS);
        const int n    = ch * CH_PTS + o;

        // independent, coalesced loads (point + normal together)
        float x = 0.f, y = 0.f, z = 0.f, nx = 0.f, ny = 0.f, nz = 0.f;
        if (ok) {
            x  = boundary[0 * NN + n];
            y  = boundary[1 * NN + n];
            z  = boundary[2 * NN + n];
            nx = nrms[0 * NN + n];
            ny = nrms[1 * NN + n];
            nz = nrms[2 * NN + n];
        }
        const float c = 0.5f * fmaf(x, x, fmaf(y, y, z * z));
        const float q = fmaf(nwx, x, fmaf(nwy, y, fmaf(nwz, z, c)));

        int cand = (ok && q == vmin) ? n : 0x7FFFFFFF;
        #pragma unroll
        for (int off = 16; off > 0; off >>= 1)
            cand = min(cand, __shfl_xor_sync(0xFFFFFFFFu, cand, off));
        // cand == exact winning n (lowest). Winner lane = cand - base.

        // speculative per-lane value; select the winner's via one shfl
        const float d = (-nwx - x) * nx + (-nwy - y) * ny + (-nwz - z) * nz;
        const float v = (d > 0.0f) ? (d + 1.0f) : expf(0.5f * d);  // ExpRelu
        vq[u] = __shfl_sync(0xFFFFFFFFu, v, cand - base);
    }

    __shared__ float sh[8 * QPW];
    if (lane == 0) {
        #pragma unroll
        for (int u = 0; u < QPW; ++u) sh[warp * QPW + u] = vq[u];
    }
    __syncthreads();

    __shared__ int s_last;
    if (threadIdx.x == 0) {
        float s = 0.0f;
        #pragma unroll
        for (int k = 0; k < 8 * QPW; ++k) s += sh[k];   // fixed order
        g_part[blockIdx.x] = s;
        __threadfence();
        const int old = atomicAdd(&g_cnt, 1);
        s_last = (old == NRED - 1) ? 1 : 0;
    }
    __syncthreads();

    if (s_last) {
        __shared__ float acc[THREADS];
        const int tid = threadIdx.x;
        float s = 0.0f;
        for (int k = tid; k < NRED; k += THREADS) s += g_part[k];
        acc[tid] = s;
        __syncthreads();
        #pragma unroll
        for (int o = THREADS / 2; o > 0; o >>= 1) {
            if (tid < o) acc[tid] += acc[tid + o];
            __syncthreads();
        }
        if (tid == 0) {
            out[0] = acc[0] * (1.0f / (float)NQ);
            g_cnt = 0;   // replay-safe reset
        }
    }
}

// ---------------------------------------------------------------------------
extern "C" void kernel_launch(void* const* d_in, const int* in_sizes, int n_in,
                              void* d_out, int out_size)
{
    const float* poses    = (const float*)d_in[0];  // [64,4,4]
    const float* wpts     = (const float*)d_in[1];  // [64,100,3]
    const float* boundary = (const float*)d_in[2];  // [4,20000]
    const float* nrms     = (const float*)d_in[3];  // [3,20000]
    float* out = (float*)d_out;

    dim3 gridn(NCH, NTILE);
    nn_kernel<<<gridn, THREADS>>>(poses, wpts, boundary);
    reduce_kernel<<<NRED, THREADS>>>(poses, wpts, boundary, nrms, out);
}